// round 11
// baseline (speedup 1.0000x reference)
#include <cuda_runtime.h>
#include <cuda_fp16.h>

// C3 sparse-connectivity conv via fp16 mma.sync (f32 accum).
// x: [32,6,512,512] f32, weight: [16,6,5,5] f32, bias: [16] f32
// out: [32,16,508,508] f32
//
// CTA = 64 px (x) * 16 output rows (y) * 16 oc, one batch image.
// Warp = TWO adjacent output rows: input rows r..r+5 loaded once as per-row
// register fragments, composed into k16 MMAs for BOTH outputs (A smem traffic
// per output cut 1.67x; B reused 2x). Vertical ky pairs -> m16n8k16, ky=4
// tail -> m16n8k8. All A loads conflict-free LDS.32.

#define OW 508
#define OH 508
#define IW 512
#define IH 512
#define TW 64
#define TH 16
#define PW 68             // TW + 4
#define PH 20             // TH + 4
#define PLANE (IH * IW)

// smem layout (bytes)
#define SA     0                        // patch [PH][PW] x 16B = 21760
#define SB16   21760                    // [kx][p][half][n][t] uint2 = 6400
#define SBT    28160                    // [kx][half][n][t] u32 = 1280
#define SBIAS  29440                    // 16 f32
#define SMEM_TOTAL 29504

__constant__ unsigned CONN[16] = {
    0x07, 0x0E, 0x1C, 0x38, 0x31, 0x23, 0x0F, 0x1E,
    0x3C, 0x39, 0x33, 0x27, 0x1B, 0x36, 0x2D, 0x3F};

__device__ __forceinline__ unsigned pack_h2(float a, float b) {
    __half2 h = __floats2half2_rn(a, b);
    return *reinterpret_cast<unsigned*>(&h);
}
__device__ __forceinline__ void mma16816(float* c, unsigned a0, unsigned a1,
                                         unsigned a2, unsigned a3,
                                         unsigned b0, unsigned b1) {
    asm volatile(
        "mma.sync.aligned.m16n8k16.row.col.f32.f16.f16.f32 "
        "{%0,%1,%2,%3}, {%4,%5,%6,%7}, {%8,%9}, {%0,%1,%2,%3};"
        : "+f"(c[0]), "+f"(c[1]), "+f"(c[2]), "+f"(c[3])
        : "r"(a0), "r"(a1), "r"(a2), "r"(a3), "r"(b0), "r"(b1));
}
__device__ __forceinline__ void mma16808(float* c, unsigned a0, unsigned a1,
                                         unsigned b0) {
    asm volatile(
        "mma.sync.aligned.m16n8k8.row.col.f32.f16.f16.f32 "
        "{%0,%1,%2,%3}, {%4,%5}, {%6}, {%0,%1,%2,%3};"
        : "+f"(c[0]), "+f"(c[1]), "+f"(c[2]), "+f"(c[3])
        : "r"(a0), "r"(a1), "r"(b0));
}

__global__ void __launch_bounds__(256, 2)
c3_hmma(const float* __restrict__ x,
        const float* __restrict__ wgt,
        const float* __restrict__ bias,
        float* __restrict__ out)
{
    __shared__ __align__(16) char smem[SMEM_TOTAL];

    const int tid = threadIdx.x;
    const int x0 = blockIdx.x * TW;
    const int y0 = blockIdx.y * TH;
    const int b  = blockIdx.z;

    // ---- channels-last fp16 patch: [row][px][ic0..5, 0, 0] ----
    const float* xb = x + (size_t)b * 6 * PLANE;
    for (int i = tid; i < PH * PW; i += 256) {
        int row = i / PW, col = i % PW;
        int gy = y0 + row, gx = x0 + col;
        uint4 v = make_uint4(0u, 0u, 0u, 0u);
        if (gy < IH && gx < IW) {
            const float* p = xb + (size_t)gy * IW + gx;
            v.x = pack_h2(p[0],         p[PLANE]);
            v.y = pack_h2(p[2 * PLANE], p[3 * PLANE]);
            v.z = pack_h2(p[4 * PLANE], p[5 * PLANE]);
        }
        *reinterpret_cast<uint4*>(smem + SA + i * 16) = v;
    }
    // ---- k16 B tiles (vertical ky pairs): [kx][p][half][n][t] uint2 ----
    for (int i = tid; i < 640; i += 256) {
        int t    = i & 3;
        int n    = (i >> 2) & 7;
        int half = (i >> 5) & 1;
        int p    = (i >> 6) & 1;
        int kx   = i >> 7;
        int oc = half * 8 + n;
        unsigned m = CONN[oc];
        uint2 w = make_uint2(0u, 0u);
        if (t < 3) {
            int ia = 2 * t, ib = 2 * t + 1;
            const float* wp = wgt + oc * 150;
            float la = (m & (1u << ia)) ? wp[ia * 25 + (2 * p) * 5 + kx] : 0.f;
            float lb = (m & (1u << ib)) ? wp[ib * 25 + (2 * p) * 5 + kx] : 0.f;
            float ha = (m & (1u << ia)) ? wp[ia * 25 + (2 * p + 1) * 5 + kx] : 0.f;
            float hb = (m & (1u << ib)) ? wp[ib * 25 + (2 * p + 1) * 5 + kx] : 0.f;
            w.x = pack_h2(la, lb);
            w.y = pack_h2(ha, hb);
        }
        *reinterpret_cast<uint2*>(smem + SB16 + i * 8) = w;
    }
    // ---- tail (ky=4) B tiles: [kx][half][n][t] u32 ----
    for (int i = tid; i < 320; i += 256) {
        int t    = i & 3;
        int n    = (i >> 2) & 7;
        int half = (i >> 5) & 1;
        int kx   = i >> 6;
        int oc = half * 8 + n;
        unsigned m = CONN[oc];
        unsigned w = 0u;
        if (t < 3) {
            int ia = 2 * t, ib = 2 * t + 1;
            const float* wp = wgt + oc * 150;
            float a = (m & (1u << ia)) ? wp[ia * 25 + 20 + kx] : 0.f;
            float c = (m & (1u << ib)) ? wp[ib * 25 + 20 + kx] : 0.f;
            w = pack_h2(a, c);
        }
        *reinterpret_cast<unsigned*>(smem + SBT + i * 4) = w;
    }
    if (tid < 16)
        reinterpret_cast<float*>(smem + SBIAS)[tid] = bias[tid];
    __syncthreads();

    const int wid  = tid >> 5;
    const int lane = tid & 31;
    const int g = lane >> 2;     // 0..7
    const int t = lane & 3;      // 0..3
    const int r0 = wid * 2;      // first of the warp's two output rows

    // acc[row(2)][m(4)][half(2)][c0..3]
    float acc[2][4][2][4];
    {
        const float* bs = reinterpret_cast<const float*>(smem + SBIAS);
#pragma unroll
        for (int h = 0; h < 2; ++h) {
            float b0 = bs[h * 8 + 2 * t];
            float b1 = bs[h * 8 + 2 * t + 1];
#pragma unroll
            for (int rr = 0; rr < 2; ++rr)
#pragma unroll
                for (int m = 0; m < 4; ++m) {
                    acc[rr][m][h][0] = b0; acc[rr][m][h][1] = b1;
                    acc[rr][m][h][2] = b0; acc[rr][m][h][3] = b1;
                }
        }
    }

#pragma unroll 1
    for (int kx = 0; kx < 5; ++kx) {
        // B fragments for this kx (shared by both output rows)
        uint2 bh[2][2];
        unsigned bt[2];
#pragma unroll
        for (int p = 0; p < 2; ++p) {
            const char* bb = smem + SB16 + ((kx * 2 + p) * 2) * 256 + lane * 8;
            bh[p][0] = *reinterpret_cast<const uint2*>(bb);
            bh[p][1] = *reinterpret_cast<const uint2*>(bb + 256);
        }
        {
            const char* bb = smem + SBT + (kx * 2) * 128 + lane * 4;
            bt[0] = *reinterpret_cast<const unsigned*>(bb);
            bt[1] = *reinterpret_cast<const unsigned*>(bb + 128);
        }

        const char* base = smem + SA + (r0 * PW + kx) * 16 + g * 16 + t * 4;
#pragma unroll
        for (int m = 0; m < 4; ++m) {
            const char* ap = base + m * 256;
            // per-input-row fragments for rows r0..r0+5
            unsigned a[6][2];
#pragma unroll
            for (int i = 0; i < 6; ++i) {
                a[i][0] = *reinterpret_cast<const unsigned*>(ap + i * (PW * 16));
                a[i][1] = *reinterpret_cast<const unsigned*>(ap + i * (PW * 16) + 128);
            }
            // output row 0: pairs (0,1),(2,3), tail 4
#pragma unroll
            for (int p = 0; p < 2; ++p) {
#pragma unroll
                for (int h = 0; h < 2; ++h)
                    mma16816(acc[0][m][h],
                             a[2 * p][0], a[2 * p][1],
                             a[2 * p + 1][0], a[2 * p + 1][1],
                             bh[p][h].x, bh[p][h].y);
            }
#pragma unroll
            for (int h = 0; h < 2; ++h)
                mma16808(acc[0][m][h], a[4][0], a[4][1], bt[h]);
            // output row 1: pairs (1,2),(3,4), tail 5
#pragma unroll
            for (int p = 0; p < 2; ++p) {
#pragma unroll
                for (int h = 0; h < 2; ++h)
                    mma16816(acc[1][m][h],
                             a[1 + 2 * p][0], a[1 + 2 * p][1],
                             a[2 + 2 * p][0], a[2 + 2 * p][1],
                             bh[p][h].x, bh[p][h].y);
            }
#pragma unroll
            for (int h = 0; h < 2; ++h)
                mma16808(acc[1][m][h], a[5][0], a[5][1], bt[h]);
        }
    }

    // ---- store: c0=(px g, oc 2t), c1=(g,2t+1), c2=(g+8,2t), c3=(g+8,2t+1) ----
#pragma unroll
    for (int rr = 0; rr < 2; ++rr) {
        const int oy = y0 + r0 + rr;
        if (oy >= OH) continue;
#pragma unroll 1
        for (int m = 0; m < 4; ++m) {
            int ox0 = x0 + m * 16 + g;   // <= 503 always valid
            int ox1 = ox0 + 8;           // may reach 511 -> guard
#pragma unroll
            for (int h = 0; h < 2; ++h) {
                int oc0 = h * 8 + 2 * t;
                size_t base0 = (((size_t)b * 16 + oc0) * OH + oy) * OW;
                size_t base1 = base0 + (size_t)OH * OW;
                out[base0 + ox0] = acc[rr][m][h][0];
                out[base1 + ox0] = acc[rr][m][h][1];
                if (ox1 < OW) {
                    out[base0 + ox1] = acc[rr][m][h][2];
                    out[base1 + ox1] = acc[rr][m][h][3];
                }
            }
        }
    }
}

extern "C" void kernel_launch(void* const* d_in, const int* in_sizes, int n_in,
                              void* d_out, int out_size)
{
    const float* x    = (const float*)d_in[0];  // [32,6,512,512]
    const float* wgt  = (const float*)d_in[1];  // [16,6,5,5]
    const float* bias = (const float*)d_in[2];  // [16]
    float* out = (float*)d_out;                 // [32,16,508,508]

    dim3 grid((OW + TW - 1) / TW,    // 8
              (OH + TH - 1) / TH,    // 32
              32);                   // batch
    c3_hmma<<<grid, 256>>>(x, wgt, bias, out);
}

// round 12
// speedup vs baseline: 1.5398x; 1.5398x over previous
#include <cuda_runtime.h>
#include <cuda_fp16.h>

// C3 sparse-connectivity conv via fp16 mma.sync (f32 accum).
// x: [32,6,512,512] f32, weight: [16,6,5,5] f32, bias: [16] f32
// out: [32,16,508,508] f32
//
// CTA = 32 px (x) * 16 output rows (y) * 16 oc, one batch image.
// Warp = TWO adjacent output rows x 32 px x 16 oc: the 6 input-row fragments
// are loaded once into registers and composed into k16 MMAs for BOTH rows
// (A smem traffic per output cut 1.67x, B reused 2x). Small accumulator
// (32 regs) keeps total regs ~70 -> 3 CTAs/SM, 24 warps, no spills.
// Vertical ky pairs -> m16n8k16, ky=4 tail -> m16n8k8.

#define OW 508
#define OH 508
#define IW 512
#define IH 512
#define TW 32
#define TH 16
#define PW 36             // TW + 4
#define PH 20             // TH + 4
#define PLANE (IH * IW)

// smem layout (bytes)
#define SA     0                        // patch [PH][PW] x 16B = 11520
#define SB16   11520                    // [kx][p][half][n][t] uint2 = 6400
#define SBT    17920                    // [kx][half][n][t] u32 = 1280
#define SBIAS  19200                    // 16 f32
#define SMEM_TOTAL 19264

__constant__ unsigned CONN[16] = {
    0x07, 0x0E, 0x1C, 0x38, 0x31, 0x23, 0x0F, 0x1E,
    0x3C, 0x39, 0x33, 0x27, 0x1B, 0x36, 0x2D, 0x3F};

__device__ __forceinline__ unsigned pack_h2(float a, float b) {
    __half2 h = __floats2half2_rn(a, b);
    return *reinterpret_cast<unsigned*>(&h);
}
__device__ __forceinline__ void mma16816(float* c, unsigned a0, unsigned a1,
                                         unsigned a2, unsigned a3,
                                         unsigned b0, unsigned b1) {
    asm volatile(
        "mma.sync.aligned.m16n8k16.row.col.f32.f16.f16.f32 "
        "{%0,%1,%2,%3}, {%4,%5,%6,%7}, {%8,%9}, {%0,%1,%2,%3};"
        : "+f"(c[0]), "+f"(c[1]), "+f"(c[2]), "+f"(c[3])
        : "r"(a0), "r"(a1), "r"(a2), "r"(a3), "r"(b0), "r"(b1));
}
__device__ __forceinline__ void mma16808(float* c, unsigned a0, unsigned a1,
                                         unsigned b0) {
    asm volatile(
        "mma.sync.aligned.m16n8k8.row.col.f32.f16.f16.f32 "
        "{%0,%1,%2,%3}, {%4,%5}, {%6}, {%0,%1,%2,%3};"
        : "+f"(c[0]), "+f"(c[1]), "+f"(c[2]), "+f"(c[3])
        : "r"(a0), "r"(a1), "r"(b0));
}

__global__ void __launch_bounds__(256, 3)
c3_hmma(const float* __restrict__ x,
        const float* __restrict__ wgt,
        const float* __restrict__ bias,
        float* __restrict__ out)
{
    __shared__ __align__(16) char smem[SMEM_TOTAL];

    const int tid = threadIdx.x;
    const int x0 = blockIdx.x * TW;
    const int y0 = blockIdx.y * TH;
    const int b  = blockIdx.z;

    // ---- channels-last fp16 patch: [row][px][ic0..5, 0, 0] ----
    const float* xb = x + (size_t)b * 6 * PLANE;
    for (int i = tid; i < PH * PW; i += 256) {
        int row = i / PW, col = i % PW;
        int gy = y0 + row, gx = x0 + col;
        uint4 v = make_uint4(0u, 0u, 0u, 0u);
        if (gy < IH && gx < IW) {
            const float* p = xb + (size_t)gy * IW + gx;
            v.x = pack_h2(p[0],         p[PLANE]);
            v.y = pack_h2(p[2 * PLANE], p[3 * PLANE]);
            v.z = pack_h2(p[4 * PLANE], p[5 * PLANE]);
        }
        *reinterpret_cast<uint4*>(smem + SA + i * 16) = v;
    }
    // ---- k16 B tiles (vertical ky pairs): [kx][p][half][n][t] uint2 ----
    for (int i = tid; i < 640; i += 256) {
        int t    = i & 3;
        int n    = (i >> 2) & 7;
        int half = (i >> 5) & 1;
        int p    = (i >> 6) & 1;
        int kx   = i >> 7;
        int oc = half * 8 + n;
        unsigned m = CONN[oc];
        uint2 w = make_uint2(0u, 0u);
        if (t < 3) {
            int ia = 2 * t, ib = 2 * t + 1;
            const float* wp = wgt + oc * 150;
            float la = (m & (1u << ia)) ? wp[ia * 25 + (2 * p) * 5 + kx] : 0.f;
            float lb = (m & (1u << ib)) ? wp[ib * 25 + (2 * p) * 5 + kx] : 0.f;
            float ha = (m & (1u << ia)) ? wp[ia * 25 + (2 * p + 1) * 5 + kx] : 0.f;
            float hb = (m & (1u << ib)) ? wp[ib * 25 + (2 * p + 1) * 5 + kx] : 0.f;
            w.x = pack_h2(la, lb);
            w.y = pack_h2(ha, hb);
        }
        *reinterpret_cast<uint2*>(smem + SB16 + i * 8) = w;
    }
    // ---- tail (ky=4) B tiles: [kx][half][n][t] u32 ----
    for (int i = tid; i < 320; i += 256) {
        int t    = i & 3;
        int n    = (i >> 2) & 7;
        int half = (i >> 5) & 1;
        int kx   = i >> 6;
        int oc = half * 8 + n;
        unsigned m = CONN[oc];
        unsigned w = 0u;
        if (t < 3) {
            int ia = 2 * t, ib = 2 * t + 1;
            const float* wp = wgt + oc * 150;
            float a = (m & (1u << ia)) ? wp[ia * 25 + 20 + kx] : 0.f;
            float c = (m & (1u << ib)) ? wp[ib * 25 + 20 + kx] : 0.f;
            w = pack_h2(a, c);
        }
        *reinterpret_cast<unsigned*>(smem + SBT + i * 4) = w;
    }
    if (tid < 16)
        reinterpret_cast<float*>(smem + SBIAS)[tid] = bias[tid];
    __syncthreads();

    const int wid  = tid >> 5;
    const int lane = tid & 31;
    const int g = lane >> 2;     // 0..7
    const int t = lane & 3;      // 0..3
    const int r0 = wid * 2;      // first of the warp's two output rows

    // acc[row(2)][m(2)][half(2)][c0..3] = 32 regs
    float acc[2][2][2][4];
    {
        const float* bs = reinterpret_cast<const float*>(smem + SBIAS);
#pragma unroll
        for (int h = 0; h < 2; ++h) {
            float b0 = bs[h * 8 + 2 * t];
            float b1 = bs[h * 8 + 2 * t + 1];
#pragma unroll
            for (int rr = 0; rr < 2; ++rr)
#pragma unroll
                for (int m = 0; m < 2; ++m) {
                    acc[rr][m][h][0] = b0; acc[rr][m][h][1] = b1;
                    acc[rr][m][h][2] = b0; acc[rr][m][h][3] = b1;
                }
        }
    }

#pragma unroll 1
    for (int kx = 0; kx < 5; ++kx) {
        // B fragments for this kx (shared by both rows and both m-tiles)
        uint2 bh[2][2];
        unsigned bt[2];
#pragma unroll
        for (int p = 0; p < 2; ++p) {
            const char* bb = smem + SB16 + ((kx * 2 + p) * 2) * 256 + lane * 8;
            bh[p][0] = *reinterpret_cast<const uint2*>(bb);
            bh[p][1] = *reinterpret_cast<const uint2*>(bb + 256);
        }
        {
            const char* bb = smem + SBT + (kx * 2) * 128 + lane * 4;
            bt[0] = *reinterpret_cast<const unsigned*>(bb);
            bt[1] = *reinterpret_cast<const unsigned*>(bb + 128);
        }

        const char* base = smem + SA + (r0 * PW + kx) * 16 + g * 16 + t * 4;
#pragma unroll
        for (int m = 0; m < 2; ++m) {
            const char* ap = base + m * 256;
            // per-input-row fragments for rows r0..r0+5 (shared by both outputs)
            unsigned a[6][2];
#pragma unroll
            for (int i = 0; i < 6; ++i) {
                a[i][0] = *reinterpret_cast<const unsigned*>(ap + i * (PW * 16));
                a[i][1] = *reinterpret_cast<const unsigned*>(ap + i * (PW * 16) + 128);
            }
            // output row 0: ky pairs (0,1),(2,3), tail 4
#pragma unroll
            for (int p = 0; p < 2; ++p)
#pragma unroll
                for (int h = 0; h < 2; ++h)
                    mma16816(acc[0][m][h],
                             a[2 * p][0], a[2 * p][1],
                             a[2 * p + 1][0], a[2 * p + 1][1],
                             bh[p][h].x, bh[p][h].y);
#pragma unroll
            for (int h = 0; h < 2; ++h)
                mma16808(acc[0][m][h], a[4][0], a[4][1], bt[h]);
            // output row 1: ky pairs (1,2),(3,4), tail 5
#pragma unroll
            for (int p = 0; p < 2; ++p)
#pragma unroll
                for (int h = 0; h < 2; ++h)
                    mma16816(acc[1][m][h],
                             a[1 + 2 * p][0], a[1 + 2 * p][1],
                             a[2 + 2 * p][0], a[2 + 2 * p][1],
                             bh[p][h].x, bh[p][h].y);
#pragma unroll
            for (int h = 0; h < 2; ++h)
                mma16808(acc[1][m][h], a[5][0], a[5][1], bt[h]);
        }
    }

    // ---- store: c0=(px g, oc 2t), c1=(g,2t+1), c2=(g+8,2t), c3=(g+8,2t+1) ----
#pragma unroll
    for (int rr = 0; rr < 2; ++rr) {
        const int oy = y0 + r0 + rr;
        if (oy >= OH) continue;
#pragma unroll 1
        for (int m = 0; m < 2; ++m) {
            int ox0 = x0 + m * 16 + g;   // <= 480+16+7 = 503, always valid
            int ox1 = ox0 + 8;           // may reach 511 -> guard
#pragma unroll
            for (int h = 0; h < 2; ++h) {
                int oc0 = h * 8 + 2 * t;
                size_t base0 = (((size_t)b * 16 + oc0) * OH + oy) * OW;
                size_t base1 = base0 + (size_t)OH * OW;
                out[base0 + ox0] = acc[rr][m][h][0];
                out[base1 + ox0] = acc[rr][m][h][1];
                if (ox1 < OW) {
                    out[base0 + ox1] = acc[rr][m][h][2];
                    out[base1 + ox1] = acc[rr][m][h][3];
                }
            }
        }
    }
}

extern "C" void kernel_launch(void* const* d_in, const int* in_sizes, int n_in,
                              void* d_out, int out_size)
{
    const float* x    = (const float*)d_in[0];  // [32,6,512,512]
    const float* wgt  = (const float*)d_in[1];  // [16,6,5,5]
    const float* bias = (const float*)d_in[2];  // [16]
    float* out = (float*)d_out;                 // [32,16,508,508]

    dim3 grid((OW + TW - 1) / TW,    // 16
              (OH + TH - 1) / TH,    // 32
              32);                   // batch
    c3_hmma<<<grid, 256>>>(x, wgt, bias, out);
}

// round 15
// speedup vs baseline: 1.9119x; 1.2416x over previous
#include <cuda_runtime.h>
#include <cuda_fp16.h>

// C3 sparse-connectivity conv via fp16 mma.sync (f32 accum).
// x: [32,6,512,512] f32, weight: [16,6,5,5] f32, bias: [16] f32
// out: [32,16,508,508] f32
//
// CTA = 64 px (x) * 8 output rows (y) * 16 oc, one batch image. Warp = 1 row.
// Mainloop (identical to the 277us round-10 kernel): per kx, vertical ky
// pairs (0,1),(2,3) -> m16n8k16, ky=4 -> m16n8k8; channels-last fp16 patch,
// all A loads conflict-free LDS.32.
// NEW: epilogue stages acc in smem ([oc][row][px], plane stride 516 floats
// -> conflict-free STS scatter) then writes fully-coalesced STG.128,
// replacing ~256 scattered-store wavefronts/warp with ~96.

#define OW 508
#define OH 508
#define IW 512
#define IH 512
#define TW 64
#define TH 8
#define PW 68             // TW + 4
#define PH 12             // TH + 4
#define PLANE (IH * IW)

// mainloop smem layout (bytes); epilogue stage overlays from 0
#define SA     0                        // patch [PH][PW] x 16B = 13056
#define SB16   13056                    // [kx][p][half][n][t] uint2 = 6400
#define SBT    19456                    // [kx][half][n][t] u32 = 1280
#define SBIAS  20736                    // 16 f32
#define STAGE_STRIDE 516                // floats per oc plane (8*64 + 4 pad)
#define SMEM_TOTAL (16 * STAGE_STRIDE * 4)   // 33024 >= 20800

__constant__ unsigned CONN[16] = {
    0x07, 0x0E, 0x1C, 0x38, 0x31, 0x23, 0x0F, 0x1E,
    0x3C, 0x39, 0x33, 0x27, 0x1B, 0x36, 0x2D, 0x3F};

__device__ __forceinline__ unsigned pack_h2(float a, float b) {
    __half2 h = __floats2half2_rn(a, b);
    return *reinterpret_cast<unsigned*>(&h);
}
__device__ __forceinline__ void mma16816(float* c, unsigned a0, unsigned a1,
                                         unsigned a2, unsigned a3,
                                         unsigned b0, unsigned b1) {
    asm volatile(
        "mma.sync.aligned.m16n8k16.row.col.f32.f16.f16.f32 "
        "{%0,%1,%2,%3}, {%4,%5,%6,%7}, {%8,%9}, {%0,%1,%2,%3};"
        : "+f"(c[0]), "+f"(c[1]), "+f"(c[2]), "+f"(c[3])
        : "r"(a0), "r"(a1), "r"(a2), "r"(a3), "r"(b0), "r"(b1));
}
__device__ __forceinline__ void mma16808(float* c, unsigned a0, unsigned a1,
                                         unsigned b0) {
    asm volatile(
        "mma.sync.aligned.m16n8k8.row.col.f32.f16.f16.f32 "
        "{%0,%1,%2,%3}, {%4,%5}, {%6}, {%0,%1,%2,%3};"
        : "+f"(c[0]), "+f"(c[1]), "+f"(c[2]), "+f"(c[3])
        : "r"(a0), "r"(a1), "r"(b0));
}

__global__ void __launch_bounds__(256, 3)
c3_hmma(const float* __restrict__ x,
        const float* __restrict__ wgt,
        const float* __restrict__ bias,
        float* __restrict__ out)
{
    __shared__ __align__(16) char smem[SMEM_TOTAL];

    const int tid = threadIdx.x;
    const int x0 = blockIdx.x * TW;
    const int y0 = blockIdx.y * TH;
    const int b  = blockIdx.z;

    // ---- channels-last fp16 patch: [row][px][ic0..5, 0, 0] ----
    const float* xb = x + (size_t)b * 6 * PLANE;
    for (int i = tid; i < PH * PW; i += 256) {
        int row = i / PW, col = i % PW;
        int gy = y0 + row, gx = x0 + col;
        uint4 v = make_uint4(0u, 0u, 0u, 0u);
        if (gy < IH && gx < IW) {
            const float* p = xb + (size_t)gy * IW + gx;
            v.x = pack_h2(p[0],         p[PLANE]);
            v.y = pack_h2(p[2 * PLANE], p[3 * PLANE]);
            v.z = pack_h2(p[4 * PLANE], p[5 * PLANE]);
        }
        *reinterpret_cast<uint4*>(smem + SA + i * 16) = v;
    }
    // ---- k16 B tiles (vertical ky pairs): [kx][p][half][n][t] uint2 ----
    for (int i = tid; i < 640; i += 256) {
        int t    = i & 3;
        int n    = (i >> 2) & 7;
        int half = (i >> 5) & 1;
        int p    = (i >> 6) & 1;
        int kx   = i >> 7;
        int oc = half * 8 + n;
        unsigned m = CONN[oc];
        uint2 w = make_uint2(0u, 0u);
        if (t < 3) {
            int ia = 2 * t, ib = 2 * t + 1;
            const float* wp = wgt + oc * 150;
            float la = (m & (1u << ia)) ? wp[ia * 25 + (2 * p) * 5 + kx] : 0.f;
            float lb = (m & (1u << ib)) ? wp[ib * 25 + (2 * p) * 5 + kx] : 0.f;
            float ha = (m & (1u << ia)) ? wp[ia * 25 + (2 * p + 1) * 5 + kx] : 0.f;
            float hb = (m & (1u << ib)) ? wp[ib * 25 + (2 * p + 1) * 5 + kx] : 0.f;
            w.x = pack_h2(la, lb);
            w.y = pack_h2(ha, hb);
        }
        *reinterpret_cast<uint2*>(smem + SB16 + i * 8) = w;
    }
    // ---- tail (ky=4) B tiles: [kx][half][n][t] u32 ----
    for (int i = tid; i < 320; i += 256) {
        int t    = i & 3;
        int n    = (i >> 2) & 7;
        int half = (i >> 5) & 1;
        int kx   = i >> 6;
        int oc = half * 8 + n;
        unsigned m = CONN[oc];
        unsigned w = 0u;
        if (t < 3) {
            int ia = 2 * t, ib = 2 * t + 1;
            const float* wp = wgt + oc * 150;
            float a = (m & (1u << ia)) ? wp[ia * 25 + 20 + kx] : 0.f;
            float c = (m & (1u << ib)) ? wp[ib * 25 + 20 + kx] : 0.f;
            w = pack_h2(a, c);
        }
        *reinterpret_cast<unsigned*>(smem + SBT + i * 4) = w;
    }
    if (tid < 16)
        reinterpret_cast<float*>(smem + SBIAS)[tid] = bias[tid];
    __syncthreads();

    const int wid  = tid >> 5;
    const int lane = tid & 31;
    const int g = lane >> 2;     // 0..7
    const int t = lane & 3;      // 0..3
    const int r = wid;           // output row within tile

    // acc[m(4)][half(2)][c0..3], init with bias (consumed into regs here,
    // so the stage overlay may clobber SBIAS later)
    float acc[4][2][4];
    {
        const float* bs = reinterpret_cast<const float*>(smem + SBIAS);
#pragma unroll
        for (int h = 0; h < 2; ++h) {
            float b0 = bs[h * 8 + 2 * t];
            float b1 = bs[h * 8 + 2 * t + 1];
#pragma unroll
            for (int m = 0; m < 4; ++m) {
                acc[m][h][0] = b0; acc[m][h][1] = b1;
                acc[m][h][2] = b0; acc[m][h][3] = b1;
            }
        }
    }

#pragma unroll 1
    for (int kx = 0; kx < 5; ++kx) {
        const char* base0 = smem + SA + (r * PW + kx) * 16 + g * 16 + t * 4;
#pragma unroll
        for (int p = 0; p < 2; ++p) {
            const char* bb = smem + SB16 + ((kx * 2 + p) * 2) * 256 + lane * 8;
            uint2 bh0 = *reinterpret_cast<const uint2*>(bb);
            uint2 bh1 = *reinterpret_cast<const uint2*>(bb + 256);
            const char* arow = base0 + (2 * p) * (PW * 16);
#pragma unroll
            for (int m = 0; m < 4; ++m) {
                const char* ap = arow + m * 256;
                unsigned a0 = *reinterpret_cast<const unsigned*>(ap);
                unsigned a1 = *reinterpret_cast<const unsigned*>(ap + 128);
                unsigned a2 = *reinterpret_cast<const unsigned*>(ap + PW * 16);
                unsigned a3 = *reinterpret_cast<const unsigned*>(ap + PW * 16 + 128);
                mma16816(acc[m][0], a0, a1, a2, a3, bh0.x, bh0.y);
                mma16816(acc[m][1], a0, a1, a2, a3, bh1.x, bh1.y);
            }
        }
        {
            const char* bb = smem + SBT + (kx * 2) * 128 + lane * 4;
            unsigned bt0 = *reinterpret_cast<const unsigned*>(bb);
            unsigned bt1 = *reinterpret_cast<const unsigned*>(bb + 128);
            const char* arow = base0 + 4 * (PW * 16);
#pragma unroll
            for (int m = 0; m < 4; ++m) {
                const char* ap = arow + m * 256;
                unsigned a0 = *reinterpret_cast<const unsigned*>(ap);
                unsigned a1 = *reinterpret_cast<const unsigned*>(ap + 128);
                mma16808(acc[m][0], a0, a1, bt0);
                mma16808(acc[m][1], a0, a1, bt1);
            }
        }
    }

    // ---- epilogue: stage in smem (conflict-free scatter), coalesced STG ----
    float* stg = reinterpret_cast<float*>(smem);
    __syncthreads();   // mainloop smem reads complete before overlay
    // fragment map: c0=(px m*16+g, oc h*8+2t), c1=(.., +1), c2=(px+8, ..), c3
#pragma unroll
    for (int m = 0; m < 4; ++m) {
#pragma unroll
        for (int h = 0; h < 2; ++h) {
            int oc0 = h * 8 + 2 * t;
            int px0 = m * 16 + g;
            // bank = 8t + 16m + g (+4 / +8 variants) -> all lanes distinct
            stg[oc0 * STAGE_STRIDE + r * 64 + px0]           = acc[m][h][0];
            stg[(oc0 + 1) * STAGE_STRIDE + r * 64 + px0]     = acc[m][h][1];
            stg[oc0 * STAGE_STRIDE + r * 64 + px0 + 8]       = acc[m][h][2];
            stg[(oc0 + 1) * STAGE_STRIDE + r * 64 + px0 + 8] = acc[m][h][3];
        }
    }
    __syncthreads();
    // coalesced write-out: thread k-th float4; 2048 float4 / 256 threads = 8
#pragma unroll
    for (int k = 0; k < 8; ++k) {
        int flat = k * 256 + tid;
        int px4 = flat & 15;           // float4 index within 64-px row
        int rr  = (flat >> 4) & 7;     // row
        int oc  = flat >> 7;           // 0..15
        int ox = x0 + px4 * 4;
        int oy = y0 + rr;
        if (ox < OW && oy < OH) {
            float4 v = *reinterpret_cast<const float4*>(
                &stg[oc * STAGE_STRIDE + rr * 64 + px4 * 4]);
            *reinterpret_cast<float4*>(
                &out[(((size_t)b * 16 + oc) * OH + oy) * OW + ox]) = v;
        }
    }
}

extern "C" void kernel_launch(void* const* d_in, const int* in_sizes, int n_in,
                              void* d_out, int out_size)
{
    const float* x    = (const float*)d_in[0];  // [32,6,512,512]
    const float* wgt  = (const float*)d_in[1];  // [16,6,5,5]
    const float* bias = (const float*)d_in[2];  // [16]
    float* out = (float*)d_out;                 // [32,16,508,508]

    dim3 grid((OW + TW - 1) / TW,    // 8
              (OH + TH - 1) / TH,    // 64
              32);                   // batch
    c3_hmma<<<grid, 256>>>(x, wgt, bias, out);
}

// round 17
// speedup vs baseline: 2.0229x; 1.0581x over previous
#include <cuda_runtime.h>
#include <cuda_fp16.h>

// C3 sparse-connectivity conv via fp16 mma.sync (f32 accum).
// x: [32,6,512,512] f32, weight: [16,6,5,5] f32, bias: [16] f32
// out: [32,16,508,508] f32
//
// CTA = 64 px (x) * 8 output rows (y) * 16 oc, one batch image. Warp = 1 row.
// Mainloop (identical to the 277us round-10 kernel): per kx, vertical ky
// pairs (0,1),(2,3) -> m16n8k16, ky=4 -> m16n8k8; channels-last fp16 patch,
// all A loads conflict-free LDS.32.
// Epilogue: PER-WARP smem staging in a dedicated buffer (a row's fragments
// all live in that row's warp) -> no __syncthreads at all; warp scatters
// (conflict-free STS), __syncwarp, reads back contiguous, writes STG.128.

#define OW 508
#define OH 508
#define IW 512
#define IH 512
#define TW 64
#define TH 8
#define PW 68             // TW + 4
#define PH 12             // TH + 4
#define PLANE (IH * IW)

// smem layout (bytes) — dynamic
#define SA     0                        // patch [PH][PW] x 16B = 13056
#define SB16   13056                    // [kx][p][half][n][t] uint2 = 6400
#define SBT    19456                    // [kx][half][n][t] u32 = 1280
#define SBIAS  20736                    // 16 f32
#define SSTAGE 20800                    // per-warp [16 oc][68] f32 = 4352 B x 8
#define SMEM_BYTES (SSTAGE + 8 * 16 * 68 * 4)   // 55616

__constant__ unsigned CONN[16] = {
    0x07, 0x0E, 0x1C, 0x38, 0x31, 0x23, 0x0F, 0x1E,
    0x3C, 0x39, 0x33, 0x27, 0x1B, 0x36, 0x2D, 0x3F};

__device__ __forceinline__ unsigned pack_h2(float a, float b) {
    __half2 h = __floats2half2_rn(a, b);
    return *reinterpret_cast<unsigned*>(&h);
}
__device__ __forceinline__ void mma16816(float* c, unsigned a0, unsigned a1,
                                         unsigned a2, unsigned a3,
                                         unsigned b0, unsigned b1) {
    asm volatile(
        "mma.sync.aligned.m16n8k16.row.col.f32.f16.f16.f32 "
        "{%0,%1,%2,%3}, {%4,%5,%6,%7}, {%8,%9}, {%0,%1,%2,%3};"
        : "+f"(c[0]), "+f"(c[1]), "+f"(c[2]), "+f"(c[3])
        : "r"(a0), "r"(a1), "r"(a2), "r"(a3), "r"(b0), "r"(b1));
}
__device__ __forceinline__ void mma16808(float* c, unsigned a0, unsigned a1,
                                         unsigned b0) {
    asm volatile(
        "mma.sync.aligned.m16n8k8.row.col.f32.f16.f16.f32 "
        "{%0,%1,%2,%3}, {%4,%5}, {%6}, {%0,%1,%2,%3};"
        : "+f"(c[0]), "+f"(c[1]), "+f"(c[2]), "+f"(c[3])
        : "r"(a0), "r"(a1), "r"(b0));
}

__global__ void __launch_bounds__(256, 3)
c3_hmma(const float* __restrict__ x,
        const float* __restrict__ wgt,
        const float* __restrict__ bias,
        float* __restrict__ out)
{
    extern __shared__ __align__(16) char smem[];

    const int tid = threadIdx.x;
    const int x0 = blockIdx.x * TW;
    const int y0 = blockIdx.y * TH;
    const int b  = blockIdx.z;

    // ---- channels-last fp16 patch: [row][px][ic0..5, 0, 0] ----
    const float* xb = x + (size_t)b * 6 * PLANE;
    for (int i = tid; i < PH * PW; i += 256) {
        int row = i / PW, col = i % PW;
        int gy = y0 + row, gx = x0 + col;
        uint4 v = make_uint4(0u, 0u, 0u, 0u);
        if (gy < IH && gx < IW) {
            const float* p = xb + (size_t)gy * IW + gx;
            v.x = pack_h2(p[0],         p[PLANE]);
            v.y = pack_h2(p[2 * PLANE], p[3 * PLANE]);
            v.z = pack_h2(p[4 * PLANE], p[5 * PLANE]);
        }
        *reinterpret_cast<uint4*>(smem + SA + i * 16) = v;
    }
    // ---- k16 B tiles (vertical ky pairs): [kx][p][half][n][t] uint2 ----
    for (int i = tid; i < 640; i += 256) {
        int t    = i & 3;
        int n    = (i >> 2) & 7;
        int half = (i >> 5) & 1;
        int p    = (i >> 6) & 1;
        int kx   = i >> 7;
        int oc = half * 8 + n;
        unsigned m = CONN[oc];
        uint2 w = make_uint2(0u, 0u);
        if (t < 3) {
            int ia = 2 * t, ib = 2 * t + 1;
            const float* wp = wgt + oc * 150;
            float la = (m & (1u << ia)) ? wp[ia * 25 + (2 * p) * 5 + kx] : 0.f;
            float lb = (m & (1u << ib)) ? wp[ib * 25 + (2 * p) * 5 + kx] : 0.f;
            float ha = (m & (1u << ia)) ? wp[ia * 25 + (2 * p + 1) * 5 + kx] : 0.f;
            float hb = (m & (1u << ib)) ? wp[ib * 25 + (2 * p + 1) * 5 + kx] : 0.f;
            w.x = pack_h2(la, lb);
            w.y = pack_h2(ha, hb);
        }
        *reinterpret_cast<uint2*>(smem + SB16 + i * 8) = w;
    }
    // ---- tail (ky=4) B tiles: [kx][half][n][t] u32 ----
    for (int i = tid; i < 320; i += 256) {
        int t    = i & 3;
        int n    = (i >> 2) & 7;
        int half = (i >> 5) & 1;
        int kx   = i >> 6;
        int oc = half * 8 + n;
        unsigned m = CONN[oc];
        unsigned w = 0u;
        if (t < 3) {
            int ia = 2 * t, ib = 2 * t + 1;
            const float* wp = wgt + oc * 150;
            float a = (m & (1u << ia)) ? wp[ia * 25 + 20 + kx] : 0.f;
            float c = (m & (1u << ib)) ? wp[ib * 25 + 20 + kx] : 0.f;
            w = pack_h2(a, c);
        }
        *reinterpret_cast<unsigned*>(smem + SBT + i * 4) = w;
    }
    if (tid < 16)
        reinterpret_cast<float*>(smem + SBIAS)[tid] = bias[tid];
    __syncthreads();

    const int wid  = tid >> 5;
    const int lane = tid & 31;
    const int g = lane >> 2;     // 0..7
    const int t = lane & 3;      // 0..3
    const int r = wid;           // output row within tile

    // acc[m(4)][half(2)][c0..3], init with bias
    float acc[4][2][4];
    {
        const float* bs = reinterpret_cast<const float*>(smem + SBIAS);
#pragma unroll
        for (int h = 0; h < 2; ++h) {
            float b0 = bs[h * 8 + 2 * t];
            float b1 = bs[h * 8 + 2 * t + 1];
#pragma unroll
            for (int m = 0; m < 4; ++m) {
                acc[m][h][0] = b0; acc[m][h][1] = b1;
                acc[m][h][2] = b0; acc[m][h][3] = b1;
            }
        }
    }

#pragma unroll 1
    for (int kx = 0; kx < 5; ++kx) {
        const char* base0 = smem + SA + (r * PW + kx) * 16 + g * 16 + t * 4;
#pragma unroll
        for (int p = 0; p < 2; ++p) {
            const char* bb = smem + SB16 + ((kx * 2 + p) * 2) * 256 + lane * 8;
            uint2 bh0 = *reinterpret_cast<const uint2*>(bb);
            uint2 bh1 = *reinterpret_cast<const uint2*>(bb + 256);
            const char* arow = base0 + (2 * p) * (PW * 16);
#pragma unroll
            for (int m = 0; m < 4; ++m) {
                const char* ap = arow + m * 256;
                unsigned a0 = *reinterpret_cast<const unsigned*>(ap);
                unsigned a1 = *reinterpret_cast<const unsigned*>(ap + 128);
                unsigned a2 = *reinterpret_cast<const unsigned*>(ap + PW * 16);
                unsigned a3 = *reinterpret_cast<const unsigned*>(ap + PW * 16 + 128);
                mma16816(acc[m][0], a0, a1, a2, a3, bh0.x, bh0.y);
                mma16816(acc[m][1], a0, a1, a2, a3, bh1.x, bh1.y);
            }
        }
        {
            const char* bb = smem + SBT + (kx * 2) * 128 + lane * 4;
            unsigned bt0 = *reinterpret_cast<const unsigned*>(bb);
            unsigned bt1 = *reinterpret_cast<const unsigned*>(bb + 128);
            const char* arow = base0 + 4 * (PW * 16);
#pragma unroll
            for (int m = 0; m < 4; ++m) {
                const char* ap = arow + m * 256;
                unsigned a0 = *reinterpret_cast<const unsigned*>(ap);
                unsigned a1 = *reinterpret_cast<const unsigned*>(ap + 128);
                mma16808(acc[m][0], a0, a1, bt0);
                mma16808(acc[m][1], a0, a1, bt1);
            }
        }
    }

    // ---- per-warp epilogue: no block syncs ----
    // warp r owns stage slice [16 oc][68 floats] (stride 68 => banks 8t+g(+4))
    float* ws = reinterpret_cast<float*>(smem + SSTAGE) + wid * (16 * 68);
#pragma unroll
    for (int m = 0; m < 4; ++m) {
#pragma unroll
        for (int h = 0; h < 2; ++h) {
            int oc0 = h * 8 + 2 * t;
            int px0 = m * 16 + g;
            ws[oc0 * 68 + px0]           = acc[m][h][0];
            ws[(oc0 + 1) * 68 + px0]     = acc[m][h][1];
            ws[oc0 * 68 + px0 + 8]       = acc[m][h][2];
            ws[(oc0 + 1) * 68 + px0 + 8] = acc[m][h][3];
        }
    }
    __syncwarp();
    const int oy = y0 + r;
    if (oy < OH) {
        // 16 oc * 16 float4 = 256 float4 per row; 8 per lane
#pragma unroll
        for (int k = 0; k < 8; ++k) {
            int flat = k * 32 + lane;
            int px4 = flat & 15;       // float4 index within 64-px row
            int oc  = flat >> 4;       // 0..15
            int ox = x0 + px4 * 4;
            if (ox < OW) {
                float4 v = *reinterpret_cast<const float4*>(&ws[oc * 68 + px4 * 4]);
                *reinterpret_cast<float4*>(
                    &out[(((size_t)b * 16 + oc) * OH + oy) * OW + ox]) = v;
            }
        }
    }
}

extern "C" void kernel_launch(void* const* d_in, const int* in_sizes, int n_in,
                              void* d_out, int out_size)
{
    const float* x    = (const float*)d_in[0];  // [32,6,512,512]
    const float* wgt  = (const float*)d_in[1];  // [16,6,5,5]
    const float* bias = (const float*)d_in[2];  // [16]
    float* out = (float*)d_out;                 // [32,16,508,508]

    cudaFuncSetAttribute(c3_hmma,
                         cudaFuncAttributeMaxDynamicSharedMemorySize,
                         SMEM_BYTES);

    dim3 grid((OW + TW - 1) / TW,    // 8
              (OH + TH - 1) / TH,    // 64
              32);                   // batch
    c3_hmma<<<grid, 256, SMEM_BYTES>>>(x, wgt, bias, out);
}